// round 1
// baseline (speedup 1.0000x reference)
#include <cuda_runtime.h>
#include <math.h>

// ---- problem dims ----
#define NSAMP 10000
#define LTOK  32
#define DD    300
#define HH    300
#define BB    256
#define NMX   128     // NMAX == MMAX
#define ITERS 50
#define INV_EPS 10.0f // 1/0.1

// ---- scratch (device globals; allocation-free) ----
__device__ float g_enc [NSAMP*DD];
__device__ float g_h1  [NSAMP*HH];
__device__ float g_henc[NSAMP*HH];
__device__ float g_rows[BB*NMX*HH];
__device__ float g_cols[BB*NMX*HH];
__device__ float g_invr[BB*NMX];
__device__ float g_invc[BB*NMX];
__device__ float g_Kmat[BB*NMX*NMX];
__device__ float g_Pmat[BB*NMX*NMX];
__device__ float g_attr[BB*NMX*HH];   // attended_row [B, MMAX, H]
__device__ float g_attc[BB*NMX*HH];   // attended_col [B, NMAX, H]
__device__ float g_cr  [BB*HH];
__device__ float g_cc  [BB*HH];

// ============================================================
// 1) embedding + masked mean pool:  enc[s,d]
// ============================================================
__global__ void k_embed(const int* __restrict__ data,
                        const float* __restrict__ emb,
                        float* __restrict__ enc) {
    int s = blockIdx.x;
    int t = threadIdx.x;            // 320 threads
    __shared__ int toks[LTOK];
    if (t < LTOK) toks[t] = data[s*LTOK + t];
    __syncthreads();
    int cnt = 0;
#pragma unroll
    for (int l = 0; l < LTOK; l++) cnt += (toks[l] != 0);
    float inv = 1.0f / (float)(cnt > 0 ? cnt : 1);
    if (t < DD) {
        float acc = 0.f;
#pragma unroll
        for (int l = 0; l < LTOK; l++) {
            int tok = toks[l];
            if (tok != 0) acc += emb[tok*DD + t];
        }
        enc[s*DD + t] = acc * inv;
    }
}

// ============================================================
// 2) generic SGEMM  C = relu(A[M,K] @ B[K,N] + bias)
//    BM=128 BN=64 BK=20 TM=8 TN=4, 256 threads
// ============================================================
__global__ void k_sgemm_relu(const float* __restrict__ A,
                             const float* __restrict__ Bm,
                             const float* __restrict__ bias,
                             float* __restrict__ C,
                             int M, int N, int K) {
    __shared__ float As[128*21];
    __shared__ float Bs[20*64];
    int t = threadIdx.x, tx = t & 15, ty = t >> 4;
    int mBase = blockIdx.y * 128, nBase = blockIdx.x * 64;
    float acc[8][4] = {};

    for (int k0 = 0; k0 < K; k0 += 20) {
#pragma unroll
        for (int i = 0; i < 10; i++) {
            int idx = t + i*256;
            int m = idx / 20, k = idx % 20;
            int gm = mBase + m, gk = k0 + k;
            As[m*21 + k] = (gm < M && gk < K) ? A[gm*K + gk] : 0.f;
        }
#pragma unroll
        for (int i = 0; i < 5; i++) {
            int idx = t + i*256;
            int k = idx >> 6, n = idx & 63;
            int gk = k0 + k, gn = nBase + n;
            Bs[k*64 + n] = (gk < K && gn < N) ? Bm[gk*N + gn] : 0.f;
        }
        __syncthreads();
#pragma unroll
        for (int kk = 0; kk < 20; kk++) {
            float a[8], bv[4];
#pragma unroll
            for (int i = 0; i < 8; i++) a[i] = As[(ty*8+i)*21 + kk];
#pragma unroll
            for (int j = 0; j < 4; j++) bv[j] = Bs[kk*64 + tx*4 + j];
#pragma unroll
            for (int i = 0; i < 8; i++)
#pragma unroll
                for (int j = 0; j < 4; j++) acc[i][j] += a[i]*bv[j];
        }
        __syncthreads();
    }
#pragma unroll
    for (int i = 0; i < 8; i++) {
        int gm = mBase + ty*8 + i;
        if (gm >= M) continue;
#pragma unroll
        for (int j = 0; j < 4; j++) {
            int gn = nBase + tx*4 + j;
            if (gn < N) {
                float v = acc[i][j] + bias[gn];
                C[gm*N + gn] = fmaxf(v, 0.f);
            }
        }
    }
}

// ============================================================
// 3) gather + mask + inverse norm (rows & cols)
// ============================================================
__global__ void k_gather(const float* __restrict__ henc,
                         const int* __restrict__ ridx, const int* __restrict__ rlen,
                         const int* __restrict__ cidx, const int* __restrict__ clen,
                         float* __restrict__ rows, float* __restrict__ cols,
                         float* __restrict__ invr, float* __restrict__ invc) {
    int p = blockIdx.x;               // 0..B*128-1
    int mode = blockIdx.y;            // 0 rows, 1 cols
    const int* idx = mode ? cidx : ridx;
    const int* len = mode ? clen : rlen;
    float* out = mode ? cols : rows;
    float* inv = mode ? invc : invr;
    int b = p >> 7, n = p & 127;
    bool valid = (n < len[b]);
    int src = idx[p];
    int t = threadIdx.x;              // 128 threads
    float sq = 0.f;
    for (int d = t; d < HH; d += 128) {
        float v = valid ? henc[src*HH + d] : 0.f;
        out[p*HH + d] = v;
        sq += v*v;
    }
#pragma unroll
    for (int o = 16; o; o >>= 1) sq += __shfl_down_sync(0xffffffffu, sq, o);
    __shared__ float ws[4];
    if ((t & 31) == 0) ws[t >> 5] = sq;
    __syncthreads();
    if (t == 0) {
        float tot = ws[0] + ws[1] + ws[2] + ws[3];
        inv[p] = 1.0f / (sqrtf(tot) + 1e-8f);
    }
}

// ============================================================
// 4) batched cosine cost -> Gibbs kernel K = exp(-Cm/eps)
//    one CTA per batch: 128x128 output, K=300, BK=12
// ============================================================
__global__ void k_cost(const float* __restrict__ rows,
                       const float* __restrict__ cols,
                       const float* __restrict__ invr,
                       const float* __restrict__ invc,
                       const int* __restrict__ rlen,
                       const int* __restrict__ clen,
                       float* __restrict__ Kout) {
    int b = blockIdx.x;
    __shared__ float As[128*13];
    __shared__ float Bs[128*13];
    int t = threadIdx.x, tx = t & 15, ty = t >> 4;
    const float* Ar = rows + b*NMX*HH;
    const float* Ac = cols + b*NMX*HH;
    float acc[8][8] = {};

    for (int k0 = 0; k0 < 300; k0 += 12) {
#pragma unroll
        for (int i = 0; i < 6; i++) {
            int idx = t + i*256;
            int m = idx / 12, k = idx % 12;
            As[m*13 + k] = Ar[m*300 + k0 + k];
            Bs[m*13 + k] = Ac[m*300 + k0 + k];
        }
        __syncthreads();
#pragma unroll
        for (int kk = 0; kk < 12; kk++) {
            float a[8], bv[8];
#pragma unroll
            for (int i = 0; i < 8; i++) a[i]  = As[(ty*8+i)*13 + kk];
#pragma unroll
            for (int j = 0; j < 8; j++) bv[j] = Bs[(tx*8+j)*13 + kk];
#pragma unroll
            for (int i = 0; i < 8; i++)
#pragma unroll
                for (int j = 0; j < 8; j++) acc[i][j] += a[i]*bv[j];
        }
        __syncthreads();
    }
    int rl = rlen[b], cl = clen[b];
#pragma unroll
    for (int i = 0; i < 8; i++) {
        int n = ty*8 + i;
        float ir = invr[b*NMX + n];
#pragma unroll
        for (int j = 0; j < 8; j++) {
            int m = tx*8 + j;
            float dn = acc[i][j] * ir * invc[b*NMX + m];
            float kv = (n < rl && m < cl) ? expf((dn - 1.0f) * INV_EPS) : 0.f;
            Kout[b*NMX*NMX + n*NMX + m] = kv;
        }
    }
}

// ============================================================
// 5) Sinkhorn (multiplicative form): v = a./(K u), u = b./(K^T v)
//    one CTA of 128 threads per batch, K resident in SMEM (stride 129)
// ============================================================
__global__ void k_sinkhorn(const float* __restrict__ Kg,
                           const int* __restrict__ rlen,
                           const int* __restrict__ clen,
                           float* __restrict__ P) {
    extern __shared__ float sm[];
    float* Ks = sm;                 // 128*129
    float* u  = sm + 128*129;       // 128
    float* v  = u + 128;            // 128
    int b = blockIdx.x, t = threadIdx.x;
    const float* Kb = Kg + b*NMX*NMX;
#pragma unroll 8
    for (int i = 0; i < 128; i++) Ks[i*129 + t] = Kb[i*128 + t];
    int rl = rlen[b], cl = clen[b];
    float ra = 1.0f / (float)rl;
    float rb = 1.0f / (float)cl;
    u[t] = (t < cl) ? 1.0f : 0.0f;
    __syncthreads();

    const float* Krow = Ks + t*129;
    for (int it = 0; it < ITERS; it++) {
        float s0 = 0.f, s1 = 0.f, s2 = 0.f, s3 = 0.f;
#pragma unroll
        for (int m = 0; m < 128; m += 4) {
            s0 += Krow[m+0]*u[m+0];
            s1 += Krow[m+1]*u[m+1];
            s2 += Krow[m+2]*u[m+2];
            s3 += Krow[m+3]*u[m+3];
        }
        float s = (s0+s1)+(s2+s3);
        v[t] = (t < rl) ? ra / s : 0.f;
        __syncthreads();
        float q0 = 0.f, q1 = 0.f, q2 = 0.f, q3 = 0.f;
#pragma unroll
        for (int n = 0; n < 128; n += 4) {
            q0 += Ks[(n+0)*129 + t]*v[n+0];
            q1 += Ks[(n+1)*129 + t]*v[n+1];
            q2 += Ks[(n+2)*129 + t]*v[n+2];
            q3 += Ks[(n+3)*129 + t]*v[n+3];
        }
        float q = (q0+q1)+(q2+q3);
        u[t] = (t < cl) ? rb / q : 0.f;
        __syncthreads();
    }
    float ut = u[t];
#pragma unroll 8
    for (int i = 0; i < 128; i++)
        P[b*NMX*NMX + i*128 + t] = v[i] * Ks[i*129 + t] * ut;
}

// ============================================================
// 6) attend (batched):
//    mode 0: attc[b] = P[b]   @ cols[b]   [128x128]@[128x300]
//    mode 1: attr[b] = P[b]^T @ rows[b]
// ============================================================
__global__ void k_attend(const float* __restrict__ P,
                         const float* __restrict__ rows,
                         const float* __restrict__ cols,
                         float* __restrict__ attr,
                         float* __restrict__ attc) {
    int bz = blockIdx.z;
    int b = bz >> 1, mode = bz & 1;
    const float* Pb = P + b*NMX*NMX;
    const float* Bm = mode ? (rows + b*NMX*HH) : (cols + b*NMX*HH);
    float* Cm = mode ? (attr + b*NMX*HH) : (attc + b*NMX*HH);
    __shared__ float As[128*17];
    __shared__ float Bs[16*64];
    int t = threadIdx.x, tx = t & 15, ty = t >> 4;
    int nBase = blockIdx.x * 64;
    float acc[8][4] = {};

    for (int k0 = 0; k0 < 128; k0 += 16) {
        if (mode == 0) {
#pragma unroll
            for (int i = 0; i < 8; i++) {
                int idx = t + i*256;
                int m = idx >> 4, k = idx & 15;
                As[m*17 + k] = Pb[m*128 + k0 + k];
            }
        } else {
#pragma unroll
            for (int i = 0; i < 8; i++) {
                int idx = t + i*256;
                int k = idx >> 7, m = idx & 127;
                As[m*17 + k] = Pb[(k0 + k)*128 + m];
            }
        }
#pragma unroll
        for (int i = 0; i < 4; i++) {
            int idx = t + i*256;
            int k = idx >> 6, n = idx & 63;
            int gn = nBase + n;
            Bs[k*64 + n] = (gn < HH) ? Bm[(k0 + k)*HH + gn] : 0.f;
        }
        __syncthreads();
#pragma unroll
        for (int kk = 0; kk < 16; kk++) {
            float a[8], bv[4];
#pragma unroll
            for (int i = 0; i < 8; i++) a[i] = As[(ty*8+i)*17 + kk];
#pragma unroll
            for (int j = 0; j < 4; j++) bv[j] = Bs[kk*64 + tx*4 + j];
#pragma unroll
            for (int i = 0; i < 8; i++)
#pragma unroll
                for (int j = 0; j < 4; j++) acc[i][j] += a[i]*bv[j];
        }
        __syncthreads();
    }
#pragma unroll
    for (int i = 0; i < 8; i++) {
        int m = ty*8 + i;
#pragma unroll
        for (int j = 0; j < 4; j++) {
            int gn = nBase + tx*4 + j;
            if (gn < HH) Cm[m*HH + gn] = acc[i][j];
        }
    }
}

// ============================================================
// 7) compare GEMM + fused masked row-sum:
//    out[b,h] = sum_{n<len[b]} relu( [A1|A2][b,n,:] @ Wc[:,h] + bc[h] )
//    one CTA covers all 128 rows of one batch (BM=128), K=600, BK=20
// ============================================================
__global__ void k_compare(const float* __restrict__ A1,
                          const float* __restrict__ A2,
                          const float* __restrict__ Wc,
                          const float* __restrict__ bc,
                          const int* __restrict__ len,
                          float* __restrict__ outsum) {
    int b = blockIdx.y;
    int nBase = blockIdx.x * 64;
    const float* a1 = A1 + b*NMX*HH;
    const float* a2 = A2 + b*NMX*HH;
    __shared__ float As[128*21];
    __shared__ float Bs[20*64];
    __shared__ float red[16][68];
    int t = threadIdx.x, tx = t & 15, ty = t >> 4;
    float acc[8][4] = {};

    for (int k0 = 0; k0 < 600; k0 += 20) {
#pragma unroll
        for (int i = 0; i < 10; i++) {
            int idx = t + i*256;
            int m = idx / 20, k = idx % 20;
            int gk = k0 + k;
            As[m*21 + k] = (gk < 300) ? a1[m*300 + gk] : a2[m*300 + gk - 300];
        }
#pragma unroll
        for (int i = 0; i < 5; i++) {
            int idx = t + i*256;
            int k = idx >> 6, n = idx & 63;
            int gk = k0 + k, gn = nBase + n;
            Bs[k*64 + n] = (gn < HH) ? Wc[gk*HH + gn] : 0.f;
        }
        __syncthreads();
#pragma unroll
        for (int kk = 0; kk < 20; kk++) {
            float a[8], bv[4];
#pragma unroll
            for (int i = 0; i < 8; i++) a[i] = As[(ty*8+i)*21 + kk];
#pragma unroll
            for (int j = 0; j < 4; j++) bv[j] = Bs[kk*64 + tx*4 + j];
#pragma unroll
            for (int i = 0; i < 8; i++)
#pragma unroll
                for (int j = 0; j < 4; j++) acc[i][j] += a[i]*bv[j];
        }
        __syncthreads();
    }
    int rl = len[b];
    float bcv[4], sums[4] = {0.f, 0.f, 0.f, 0.f};
#pragma unroll
    for (int j = 0; j < 4; j++) {
        int gn = nBase + tx*4 + j;
        bcv[j] = (gn < HH) ? bc[gn] : 0.f;
    }
#pragma unroll
    for (int i = 0; i < 8; i++) {
        int r = ty*8 + i;
        if (r < rl) {
#pragma unroll
            for (int j = 0; j < 4; j++)
                sums[j] += fmaxf(acc[i][j] + bcv[j], 0.f);
        }
    }
#pragma unroll
    for (int j = 0; j < 4; j++) red[ty][tx*4 + j] = sums[j];
    __syncthreads();
    if (t < 64) {
        float s = 0.f;
#pragma unroll
        for (int r = 0; r < 16; r++) s += red[r][t];
        int gn = nBase + t;
        if (gn < HH) outsum[b*HH + gn] = s;
    }
}

// ============================================================
// 8) classifier head: z = relu([cr|cc] @ Wcls + bcls); out = z @ Wout + bout
// ============================================================
__global__ void k_cls(const float* __restrict__ cr,
                      const float* __restrict__ cc,
                      const float* __restrict__ Wcls,
                      const float* __restrict__ bcls,
                      const float* __restrict__ Wout,
                      const float* __restrict__ bout,
                      float* __restrict__ out) {
    int b = blockIdx.x;
    int t = threadIdx.x;              // 320 threads (10 warps)
    __shared__ float x[2*HH];
    for (int i = t; i < 2*HH; i += 320)
        x[i] = (i < HH) ? cr[b*HH + i] : cc[b*HH + i - HH];
    __syncthreads();
    float z = 0.f;
    if (t < HH) {
        float a0 = 0.f, a1 = 0.f, a2 = 0.f, a3 = 0.f;
#pragma unroll 4
        for (int k = 0; k < 2*HH; k += 4) {
            a0 += x[k+0]*Wcls[(k+0)*HH + t];
            a1 += x[k+1]*Wcls[(k+1)*HH + t];
            a2 += x[k+2]*Wcls[(k+2)*HH + t];
            a3 += x[k+3]*Wcls[(k+3)*HH + t];
        }
        z = fmaxf((a0+a1)+(a2+a3) + bcls[t], 0.f);
    }
    float s0 = (t < HH) ? z*Wout[t*2 + 0] : 0.f;
    float s1 = (t < HH) ? z*Wout[t*2 + 1] : 0.f;
#pragma unroll
    for (int o = 16; o; o >>= 1) {
        s0 += __shfl_down_sync(0xffffffffu, s0, o);
        s1 += __shfl_down_sync(0xffffffffu, s1, o);
    }
    __shared__ float r0[10], r1[10];
    if ((t & 31) == 0) { r0[t >> 5] = s0; r1[t >> 5] = s1; }
    __syncthreads();
    if (t == 0) {
        float a = 0.f, c = 0.f;
#pragma unroll
        for (int i = 0; i < 10; i++) { a += r0[i]; c += r1[i]; }
        out[b*2 + 0] = a + bout[0];
        out[b*2 + 1] = c + bout[1];
    }
}

// ============================================================
// launch
// ============================================================
extern "C" void kernel_launch(void* const* d_in, const int* in_sizes, int n_in,
                              void* d_out, int out_size) {
    const int*   data    = (const int*)  d_in[0];
    const int*   row_idx = (const int*)  d_in[1];
    const int*   col_idx = (const int*)  d_in[2];
    const int*   row_len = (const int*)  d_in[3];
    const int*   col_len = (const int*)  d_in[4];
    const float* emb     = (const float*)d_in[5];
    const float* W1      = (const float*)d_in[6];
    const float* b1      = (const float*)d_in[7];
    const float* W2      = (const float*)d_in[8];
    const float* b2      = (const float*)d_in[9];
    const float* Wc      = (const float*)d_in[10];
    const float* bc      = (const float*)d_in[11];
    const float* Wcls    = (const float*)d_in[12];
    const float* bcls    = (const float*)d_in[13];
    const float* Wout    = (const float*)d_in[14];
    const float* bout    = (const float*)d_in[15];
    float* out = (float*)d_out;

    float *enc, *h1, *henc, *rows, *cols, *invr, *invc, *Kb, *Pb, *attr, *attc, *cr, *cc;
    cudaGetSymbolAddress((void**)&enc,  g_enc);
    cudaGetSymbolAddress((void**)&h1,   g_h1);
    cudaGetSymbolAddress((void**)&henc, g_henc);
    cudaGetSymbolAddress((void**)&rows, g_rows);
    cudaGetSymbolAddress((void**)&cols, g_cols);
    cudaGetSymbolAddress((void**)&invr, g_invr);
    cudaGetSymbolAddress((void**)&invc, g_invc);
    cudaGetSymbolAddress((void**)&Kb,   g_Kmat);
    cudaGetSymbolAddress((void**)&Pb,   g_Pmat);
    cudaGetSymbolAddress((void**)&attr, g_attr);
    cudaGetSymbolAddress((void**)&attc, g_attc);
    cudaGetSymbolAddress((void**)&cr,   g_cr);
    cudaGetSymbolAddress((void**)&cc,   g_cc);

    // 1) embedding pool
    k_embed<<<NSAMP, 320>>>(data, emb, enc);
    // 2) FFN (two relu GEMMs)
    dim3 gFFN((HH + 63)/64, (NSAMP + 127)/128);
    k_sgemm_relu<<<gFFN, 256>>>(enc, W1, b1, h1,   NSAMP, HH, DD);
    k_sgemm_relu<<<gFFN, 256>>>(h1,  W2, b2, henc, NSAMP, HH, HH);
    // 3) gather + mask + norms
    k_gather<<<dim3(BB*NMX, 2), 128>>>(henc, row_idx, row_len, col_idx, col_len,
                                       rows, cols, invr, invc);
    // 4) cosine cost -> Gibbs kernel
    k_cost<<<BB, 256>>>(rows, cols, invr, invc, row_len, col_len, Kb);
    // 5) Sinkhorn in SMEM
    int sink_smem = (128*129 + 256) * (int)sizeof(float);
    cudaFuncSetAttribute(k_sinkhorn, cudaFuncAttributeMaxDynamicSharedMemorySize, sink_smem);
    k_sinkhorn<<<BB, 128, sink_smem>>>(Kb, row_len, col_len, Pb);
    // 6) attends (batched, both directions)
    k_attend<<<dim3((HH + 63)/64, 1, 2*BB), 256>>>(Pb, rows, cols, attr, attc);
    // 7) compare + fused masked sums
    k_compare<<<dim3((HH + 63)/64, BB), 256>>>(rows, attc, Wc, bc, row_len, cr);
    k_compare<<<dim3((HH + 63)/64, BB), 256>>>(cols, attr, Wc, bc, col_len, cc);
    // 8) head
    k_cls<<<BB, 320>>>(cr, cc, Wcls, bcls, Wout, bout, out);
}

// round 2
// speedup vs baseline: 2.3152x; 2.3152x over previous
#include <cuda_runtime.h>
#include <math.h>

// ---- problem dims ----
#define NSAMP 10000
#define LTOK  32
#define DD    300
#define HH    300
#define BB    256
#define NMX   128
#define ITERS 50

// ---- scratch ----
__device__ float g_enc [NSAMP*DD];
__device__ float g_h1  [NSAMP*HH];
__device__ float g_henc[NSAMP*HH];
__device__ float g_Hc  [2*NSAMP*HH];   // [0]=henc@Wc[:300], [1]=henc@Wc[300:]
__device__ float g_invh[NSAMP];
__device__ float g_Kmat[BB*NMX*NMX];
__device__ float g_Pmat[BB*NMX*NMX];
__device__ float g_cr  [BB*HH];
__device__ float g_cc  [BB*HH];

// ============================================================
// 1) embedding + masked mean pool
// ============================================================
__global__ void k_embed(const int* __restrict__ data,
                        const float* __restrict__ emb,
                        float* __restrict__ enc) {
    int s = blockIdx.x;
    int t = threadIdx.x;            // 320 threads
    __shared__ int toks[LTOK];
    if (t < LTOK) toks[t] = data[s*LTOK + t];
    __syncthreads();
    int cnt = 0;
#pragma unroll
    for (int l = 0; l < LTOK; l++) cnt += (toks[l] != 0);
    float inv = 1.0f / (float)(cnt > 0 ? cnt : 1);
    if (t < DD) {
        float acc = 0.f;
#pragma unroll
        for (int l = 0; l < LTOK; l++) {
            int tok = toks[l];
            if (tok != 0) acc += emb[tok*DD + t];
        }
        enc[s*DD + t] = acc * inv;
    }
}

// ============================================================
// 2) SGEMM 128x128x16, TM=TN=8 (4+4 split), 256 threads
//    C = [relu](A @ (B + z*bStride) + bias) -> C + z*cStride
// ============================================================
template<bool RELU>
__global__ void k_sgemm128(const float* __restrict__ A, const float* __restrict__ B,
                           const float* __restrict__ bias, float* __restrict__ C,
                           int M, int N, int K, long bStride, long cStride) {
    B += (long)blockIdx.z * bStride;
    C += (long)blockIdx.z * cStride;
    __shared__ float As[16*132];
    __shared__ float Bs[16*128];
    int t = threadIdx.x, tx = t & 15, ty = t >> 4;
    int mBase = blockIdx.y * 128, nBase = blockIdx.x * 128;
    float acc[8][8] = {};

    for (int k0 = 0; k0 < K; k0 += 16) {
#pragma unroll
        for (int p = 0; p < 2; p++) {
            int id = p*256 + t;
            int m = id >> 2, kq = id & 3;
            int gm = mBase + m, gk = k0 + kq*4;
            float4 v = make_float4(0.f,0.f,0.f,0.f);
            if (gm < M && gk < K) v = *(const float4*)&A[(size_t)gm*K + gk];
            As[(kq*4+0)*132 + m] = v.x;
            As[(kq*4+1)*132 + m] = v.y;
            As[(kq*4+2)*132 + m] = v.z;
            As[(kq*4+3)*132 + m] = v.w;
        }
#pragma unroll
        for (int p = 0; p < 2; p++) {
            int id = p*256 + t;
            int kr = id >> 5, nq = id & 31;
            int gk = k0 + kr, gn = nBase + nq*4;
            float4 v = make_float4(0.f,0.f,0.f,0.f);
            if (gk < K && gn < N) v = *(const float4*)&B[(size_t)gk*N + gn];
            *(float4*)&Bs[kr*128 + nq*4] = v;
        }
        __syncthreads();
#pragma unroll
        for (int kk = 0; kk < 16; kk++) {
            float4 a0 = *(const float4*)&As[kk*132 + ty*4];
            float4 a1 = *(const float4*)&As[kk*132 + 64 + ty*4];
            float4 b0 = *(const float4*)&Bs[kk*128 + tx*4];
            float4 b1 = *(const float4*)&Bs[kk*128 + 64 + tx*4];
            float av[8] = {a0.x,a0.y,a0.z,a0.w,a1.x,a1.y,a1.z,a1.w};
            float bv[8] = {b0.x,b0.y,b0.z,b0.w,b1.x,b1.y,b1.z,b1.w};
#pragma unroll
            for (int i = 0; i < 8; i++)
#pragma unroll
                for (int j = 0; j < 8; j++) acc[i][j] += av[i]*bv[j];
        }
        __syncthreads();
    }
#pragma unroll
    for (int i = 0; i < 8; i++) {
        int gm = mBase + ((i < 4) ? ty*4 + i : 64 + ty*4 + i - 4);
        if (gm >= M) continue;
#pragma unroll
        for (int jh = 0; jh < 2; jh++) {
            int gn = nBase + jh*64 + tx*4;
            if (gn >= N) continue;
            float4 bb = bias ? *(const float4*)&bias[gn] : make_float4(0.f,0.f,0.f,0.f);
            float4 o;
            o.x = acc[i][jh*4+0] + bb.x;
            o.y = acc[i][jh*4+1] + bb.y;
            o.z = acc[i][jh*4+2] + bb.z;
            o.w = acc[i][jh*4+3] + bb.w;
            if (RELU) {
                o.x = fmaxf(o.x, 0.f); o.y = fmaxf(o.y, 0.f);
                o.z = fmaxf(o.z, 0.f); o.w = fmaxf(o.w, 0.f);
            }
            *(float4*)&C[(size_t)gm*N + gn] = o;
        }
    }
}

// ============================================================
// 3) per-sample inverse norm of henc
// ============================================================
__global__ void k_invnorm(const float* __restrict__ henc, float* __restrict__ invh) {
    int s = blockIdx.x * 8 + (threadIdx.x >> 5);
    int l = threadIdx.x & 31;
    if (s >= NSAMP) return;
    const float4* hp = (const float4*)(henc + (size_t)s*HH);
    float sq = 0.f;
    for (int d4 = l; d4 < 75; d4 += 32) {
        float4 v = hp[d4];
        sq += v.x*v.x + v.y*v.y + v.z*v.z + v.w*v.w;
    }
#pragma unroll
    for (int o = 16; o; o >>= 1) sq += __shfl_down_sync(0xffffffffu, sq, o);
    if (l == 0) invh[s] = 1.0f / (sqrtf(sq) + 1e-8f);
}

// ============================================================
// 4) fused gather + cosine cost + Gibbs kernel K = exp(-C/eps)
//    one CTA per batch, 128x128, K=300
// ============================================================
__global__ void k_cost(const float* __restrict__ henc, const float* __restrict__ invh,
                       const int* __restrict__ ridx, const int* __restrict__ cidx,
                       const int* __restrict__ rlen, const int* __restrict__ clen,
                       float* __restrict__ Kout) {
    int b = blockIdx.x;
    __shared__ float As[16*132], Bs[16*132];
    __shared__ int sr[128], sc[128];
    __shared__ float sir[128], sic[128];
    int t = threadIdx.x, tx = t & 15, ty = t >> 4;
    if (t < 128) {
        int i = ridx[b*128 + t];
        sr[t] = i; sir[t] = invh[i];
    } else {
        int i = cidx[b*128 + (t-128)];
        sc[t-128] = i; sic[t-128] = invh[i];
    }
    __syncthreads();

    float acc[8][8] = {};
    for (int k0 = 0; k0 < 300; k0 += 16) {
#pragma unroll
        for (int p = 0; p < 2; p++) {
            int id = p*256 + t;
            int m = id >> 2, kq = id & 3;
            int gk = k0 + kq*4;
            float4 va = make_float4(0.f,0.f,0.f,0.f), vb = va;
            if (gk < 300) {
                va = *(const float4*)&henc[(size_t)sr[m]*300 + gk];
                vb = *(const float4*)&henc[(size_t)sc[m]*300 + gk];
            }
            As[(kq*4+0)*132 + m] = va.x; As[(kq*4+1)*132 + m] = va.y;
            As[(kq*4+2)*132 + m] = va.z; As[(kq*4+3)*132 + m] = va.w;
            Bs[(kq*4+0)*132 + m] = vb.x; Bs[(kq*4+1)*132 + m] = vb.y;
            Bs[(kq*4+2)*132 + m] = vb.z; Bs[(kq*4+3)*132 + m] = vb.w;
        }
        __syncthreads();
#pragma unroll
        for (int kk = 0; kk < 16; kk++) {
            float4 a0 = *(const float4*)&As[kk*132 + ty*4];
            float4 a1 = *(const float4*)&As[kk*132 + 64 + ty*4];
            float4 b0 = *(const float4*)&Bs[kk*132 + tx*4];
            float4 b1 = *(const float4*)&Bs[kk*132 + 64 + tx*4];
            float av[8] = {a0.x,a0.y,a0.z,a0.w,a1.x,a1.y,a1.z,a1.w};
            float bv[8] = {b0.x,b0.y,b0.z,b0.w,b1.x,b1.y,b1.z,b1.w};
#pragma unroll
            for (int i = 0; i < 8; i++)
#pragma unroll
                for (int j = 0; j < 8; j++) acc[i][j] += av[i]*bv[j];
        }
        __syncthreads();
    }
    int rl = rlen[b], cl = clen[b];
    float* out = Kout + (size_t)b*NMX*NMX;
#pragma unroll
    for (int i = 0; i < 8; i++) {
        int n = (i < 4) ? ty*4 + i : 64 + ty*4 + i - 4;
        float ir = sir[n];
        bool nv = (n < rl);
#pragma unroll
        for (int jh = 0; jh < 2; jh++) {
            float4 kv;
            float r[4];
#pragma unroll
            for (int j = 0; j < 4; j++) {
                int m = jh*64 + tx*4 + j;
                float dn = acc[i][jh*4+j] * ir * sic[m];
                r[j] = (nv && m < cl) ? __expf((dn - 1.0f) * 10.0f) : 0.f;
            }
            kv.x = r[0]; kv.y = r[1]; kv.z = r[2]; kv.w = r[3];
            *(float4*)&out[n*128 + jh*64 + tx*4] = kv;
        }
    }
}

// ============================================================
// 5) Sinkhorn (multiplicative), K in SMEM pad-132 (f4-conflict-free)
//    row pass: thread-per-row float4; col pass: warp-per-32-rows
// ============================================================
__global__ void k_sinkhorn(const float* __restrict__ Kg,
                           const int* __restrict__ rlen,
                           const int* __restrict__ clen,
                           float* __restrict__ P) {
    extern __shared__ float sm[];
    float* Ks  = sm;               // 128*132
    float* u   = Ks + 128*132;     // 128
    float* v   = u + 128;          // 128
    float* red = v + 128;          // 4*128
    int b = blockIdx.x, t = threadIdx.x;
    const float* Kb = Kg + (size_t)b*NMX*NMX;
#pragma unroll 4
    for (int i = 0; i < 128; i++) Ks[i*132 + t] = Kb[i*128 + t];
    int rl = rlen[b], cl = clen[b];
    float ra = 1.0f / (float)rl, rb = 1.0f / (float)cl;
    u[t] = (t < cl) ? 1.0f : 0.0f;
    __syncthreads();

    int w = t >> 5, l = t & 31;
    const float4* Kr4 = (const float4*)(Ks + t*132);
    const float4* u4  = (const float4*)u;
    for (int it = 0; it < ITERS; it++) {
        float4 s4 = make_float4(0.f,0.f,0.f,0.f);
#pragma unroll
        for (int m = 0; m < 32; m++) {
            float4 k4 = Kr4[m], uu = u4[m];
            s4.x += k4.x*uu.x; s4.y += k4.y*uu.y;
            s4.z += k4.z*uu.z; s4.w += k4.w*uu.w;
        }
        float s = (s4.x + s4.y) + (s4.z + s4.w);
        v[t] = (t < rl) ? ra / s : 0.f;
        __syncthreads();
        float4 q4 = make_float4(0.f,0.f,0.f,0.f);
#pragma unroll
        for (int r = 0; r < 32; r++) {
            int n = w*32 + r;
            float vn = v[n];
            float4 k4 = *(const float4*)(Ks + n*132 + l*4);
            q4.x += k4.x*vn; q4.y += k4.y*vn;
            q4.z += k4.z*vn; q4.w += k4.w*vn;
        }
        *(float4*)(red + w*128 + l*4) = q4;
        __syncthreads();
        float q = red[t] + red[128 + t] + red[256 + t] + red[384 + t];
        u[t] = (t < cl) ? rb / q : 0.f;
        __syncthreads();
    }
    float ut = u[t];
    float* Pb = P + (size_t)b*NMX*NMX;
#pragma unroll 4
    for (int i = 0; i < 128; i++)
        Pb[i*128 + t] = v[i] * Ks[i*132 + t] * ut;
}

// ============================================================
// 6) P-GEMM + compare epilogue (fused):
//    mode0: cr[b,h] = sum_{n<rl} relu( (P @ Hc2[cidx])[n,h] + Hc1[ridx[n],h] + bc[h] )
//    mode1: cc[b,h] = sum_{m<cl} relu( (P^T @ Hc2[ridx])[m,h] + Hc1[cidx[m],h] + bc[h] )
//    tile: 128 rows x 64 h, K=128, 256 threads
// ============================================================
__global__ void k_pcmp(const float* __restrict__ P,
                       const float* __restrict__ Hc1, const float* __restrict__ Hc2,
                       const float* __restrict__ bc,
                       const int* __restrict__ ridx, const int* __restrict__ cidx,
                       const int* __restrict__ rlen, const int* __restrict__ clen,
                       float* __restrict__ cr, float* __restrict__ cc) {
    int b = blockIdx.z, mode = blockIdx.y;
    int hBase = blockIdx.x * 64;
    const int* gidxA = mode ? (ridx + b*128) : (cidx + b*128);  // K-dim gather (Hc2)
    const int* gidxE = mode ? (cidx + b*128) : (ridx + b*128);  // epilogue gather (Hc1)
    int len = mode ? clen[b] : rlen[b];
    const float* Pb = P + (size_t)b*NMX*NMX;

    __shared__ float As[16*132];
    __shared__ float Bs[16*64];
    __shared__ int sA[128], sE[128];
    __shared__ float redsm[16*68];
    int t = threadIdx.x, tx = t & 15, ty = t >> 4;
    if (t < 128) sA[t] = gidxA[t];
    else sE[t-128] = gidxE[t-128];
    __syncthreads();

    float acc[8][4] = {};
    for (int k0 = 0; k0 < 128; k0 += 16) {
        if (mode == 0) {
            // As[k][n] = P[n][k0+k]  (transpose-store)
#pragma unroll
            for (int p = 0; p < 2; p++) {
                int id = p*256 + t;
                int n = id >> 2, kq = id & 3;
                float4 vv = *(const float4*)&Pb[n*128 + k0 + kq*4];
                As[(kq*4+0)*132 + n] = vv.x; As[(kq*4+1)*132 + n] = vv.y;
                As[(kq*4+2)*132 + n] = vv.z; As[(kq*4+3)*132 + n] = vv.w;
            }
        } else {
            // As[k][m] = P[k0+k][m]  (natural)
#pragma unroll
            for (int p = 0; p < 2; p++) {
                int id = p*256 + t;
                int kr = id >> 5, mq = id & 31;
                float4 vv = *(const float4*)&Pb[(k0 + kr)*128 + mq*4];
                *(float4*)&As[kr*132 + mq*4] = vv;
            }
        }
        {
            int kr = t >> 4, hq = t & 15;
            int hg = hBase + hq*4;
            float4 vv = make_float4(0.f,0.f,0.f,0.f);
            if (hg < 300) vv = *(const float4*)&Hc2[(size_t)sA[k0 + kr]*300 + hg];
            *(float4*)&Bs[kr*64 + hq*4] = vv;
        }
        __syncthreads();
#pragma unroll
        for (int kk = 0; kk < 16; kk++) {
            float4 a0 = *(const float4*)&As[kk*132 + ty*4];
            float4 a1 = *(const float4*)&As[kk*132 + 64 + ty*4];
            float4 b0 = *(const float4*)&Bs[kk*64 + tx*4];
            float av[8] = {a0.x,a0.y,a0.z,a0.w,a1.x,a1.y,a1.z,a1.w};
            float bv[4] = {b0.x,b0.y,b0.z,b0.w};
#pragma unroll
            for (int i = 0; i < 8; i++)
#pragma unroll
                for (int j = 0; j < 4; j++) acc[i][j] += av[i]*bv[j];
        }
        __syncthreads();
    }

    int hg0 = hBase + tx*4;
    float4 bcv = (hg0 < 300) ? *(const float4*)&bc[hg0] : make_float4(0.f,0.f,0.f,0.f);
    float bcv_a[4] = {bcv.x, bcv.y, bcv.z, bcv.w};
    float sums[4] = {0.f, 0.f, 0.f, 0.f};
#pragma unroll
    for (int i = 0; i < 8; i++) {
        int r = (i < 4) ? ty*4 + i : 64 + ty*4 + i - 4;
        if (r < len) {
            float4 add = make_float4(0.f,0.f,0.f,0.f);
            if (hg0 < 300) add = *(const float4*)&Hc1[(size_t)sE[r]*300 + hg0];
            float ad[4] = {add.x, add.y, add.z, add.w};
#pragma unroll
            for (int j = 0; j < 4; j++)
                sums[j] += fmaxf(acc[i][j] + ad[j] + bcv_a[j], 0.f);
        }
    }
#pragma unroll
    for (int j = 0; j < 4; j++) redsm[ty*68 + tx*4 + j] = sums[j];
    __syncthreads();
    if (t < 64) {
        float s = 0.f;
#pragma unroll
        for (int r = 0; r < 16; r++) s += redsm[r*68 + t];
        int hg = hBase + t;
        if (hg < 300) {
            float* outp = mode ? cc : cr;
            outp[b*HH + hg] = s;
        }
    }
}

// ============================================================
// 7) classifier head
// ============================================================
__global__ void k_cls(const float* __restrict__ cr,
                      const float* __restrict__ cc,
                      const float* __restrict__ Wcls,
                      const float* __restrict__ bcls,
                      const float* __restrict__ Wout,
                      const float* __restrict__ bout,
                      float* __restrict__ out) {
    int b = blockIdx.x;
    int t = threadIdx.x;              // 320 threads
    __shared__ float x[2*HH];
    for (int i = t; i < 2*HH; i += 320)
        x[i] = (i < HH) ? cr[b*HH + i] : cc[b*HH + i - HH];
    __syncthreads();
    float z = 0.f;
    if (t < HH) {
        float a0 = 0.f, a1 = 0.f, a2 = 0.f, a3 = 0.f;
#pragma unroll 4
        for (int k = 0; k < 2*HH; k += 4) {
            a0 += x[k+0]*Wcls[(k+0)*HH + t];
            a1 += x[k+1]*Wcls[(k+1)*HH + t];
            a2 += x[k+2]*Wcls[(k+2)*HH + t];
            a3 += x[k+3]*Wcls[(k+3)*HH + t];
        }
        z = fmaxf((a0+a1)+(a2+a3) + bcls[t], 0.f);
    }
    float s0 = (t < HH) ? z*Wout[t*2 + 0] : 0.f;
    float s1 = (t < HH) ? z*Wout[t*2 + 1] : 0.f;
#pragma unroll
    for (int o = 16; o; o >>= 1) {
        s0 += __shfl_down_sync(0xffffffffu, s0, o);
        s1 += __shfl_down_sync(0xffffffffu, s1, o);
    }
    __shared__ float r0[10], r1[10];
    if ((t & 31) == 0) { r0[t >> 5] = s0; r1[t >> 5] = s1; }
    __syncthreads();
    if (t == 0) {
        float a = 0.f, c = 0.f;
#pragma unroll
        for (int i = 0; i < 10; i++) { a += r0[i]; c += r1[i]; }
        out[b*2 + 0] = a + bout[0];
        out[b*2 + 1] = c + bout[1];
    }
}

// ============================================================
// launch
// ============================================================
extern "C" void kernel_launch(void* const* d_in, const int* in_sizes, int n_in,
                              void* d_out, int out_size) {
    const int*   data    = (const int*)  d_in[0];
    const int*   row_idx = (const int*)  d_in[1];
    const int*   col_idx = (const int*)  d_in[2];
    const int*   row_len = (const int*)  d_in[3];
    const int*   col_len = (const int*)  d_in[4];
    const float* emb     = (const float*)d_in[5];
    const float* W1      = (const float*)d_in[6];
    const float* b1      = (const float*)d_in[7];
    const float* W2      = (const float*)d_in[8];
    const float* b2      = (const float*)d_in[9];
    const float* Wc      = (const float*)d_in[10];
    const float* bc      = (const float*)d_in[11];
    const float* Wcls    = (const float*)d_in[12];
    const float* bcls    = (const float*)d_in[13];
    const float* Wout    = (const float*)d_in[14];
    const float* bout    = (const float*)d_in[15];
    float* out = (float*)d_out;

    float *enc, *h1, *henc, *Hc, *invh, *Kb, *Pb, *cr, *cc;
    cudaGetSymbolAddress((void**)&enc,  g_enc);
    cudaGetSymbolAddress((void**)&h1,   g_h1);
    cudaGetSymbolAddress((void**)&henc, g_henc);
    cudaGetSymbolAddress((void**)&Hc,   g_Hc);
    cudaGetSymbolAddress((void**)&invh, g_invh);
    cudaGetSymbolAddress((void**)&Kb,   g_Kmat);
    cudaGetSymbolAddress((void**)&Pb,   g_Pmat);
    cudaGetSymbolAddress((void**)&cr,   g_cr);
    cudaGetSymbolAddress((void**)&cc,   g_cc);
    float* Hc1 = Hc;
    float* Hc2 = Hc + (long)NSAMP*HH;

    // 1) embedding pool
    k_embed<<<NSAMP, 320>>>(data, emb, enc);
    // 2) FFN
    dim3 gF(3, 79, 1);
    k_sgemm128<true><<<gF, 256>>>(enc, W1, b1, h1,   NSAMP, HH, DD, 0, 0);
    k_sgemm128<true><<<gF, 256>>>(h1,  W2, b2, henc, NSAMP, HH, HH, 0, 0);
    // 3) inverse norms of henc
    k_invnorm<<<(NSAMP + 7)/8, 256>>>(henc, invh);
    // 4) Hc1 = henc@Wc[:300], Hc2 = henc@Wc[300:]  (one dual launch)
    dim3 gHc(3, 79, 2);
    k_sgemm128<false><<<gHc, 256>>>(henc, Wc, nullptr, Hc,
                                    NSAMP, HH, HH, (long)HH*HH, (long)NSAMP*HH);
    // 5) fused gather + cosine cost -> Gibbs K
    k_cost<<<BB, 256>>>(henc, invh, row_idx, col_idx, row_len, col_len, Kb);
    // 6) Sinkhorn
    int sink_smem = (128*132 + 128 + 128 + 512) * (int)sizeof(float);
    cudaFuncSetAttribute(k_sinkhorn, cudaFuncAttributeMaxDynamicSharedMemorySize, sink_smem);
    k_sinkhorn<<<BB, 128, sink_smem>>>(Kb, row_len, col_len, Pb);
    // 7) fused P-GEMM + compare epilogue (both directions)
    k_pcmp<<<dim3(5, 2, BB), 256>>>(Pb, Hc1, Hc2, bc, row_idx, col_idx,
                                    row_len, col_len, cr, cc);
    // 8) head
    k_cls<<<BB, 320>>>(cr, cc, Wcls, bcls, Wout, bout, out);
}